// round 1
// baseline (speedup 1.0000x reference)
#include <cuda_runtime.h>
#include <cstdint>

#define NNODES 8192
#define FDIM 128
#define BI 64
#define BJ 128
#define THREADS 256

// Scratch (allocation-free rule: __device__ globals)
__device__ float g_Wh[NNODES * FDIM];
__device__ float g_f1[NNODES];
__device__ float g_f2[NNODES];

// ---------- helpers ----------

// exp(x) via FFMA-only exp2 (MUFU.EX2 would bottleneck at ~0.5/cyc/SM).
// Taylor deg-5 of 2^f on [-0.5, 0.5]: max rel err ~2.4e-6.
__device__ __forceinline__ float fast_exp(float x) {
    float z = x * 1.4426950408889634f;
    float n = rintf(z);
    float f = z - n;
    float p = 1.3333558e-3f;
    p = fmaf(p, f, 9.6181291e-3f);
    p = fmaf(p, f, 5.5504109e-2f);
    p = fmaf(p, f, 2.4022651e-1f);
    p = fmaf(p, f, 6.9314718e-1f);
    p = fmaf(p, f, 1.0f);
    int e = (int)n;
    float s = __int_as_float((e + 127) << 23);
    return p * s;
}

// Packed fp32x2 FMA (sm_103a; ptxas never emits this from C++ — PTX only).
__device__ __forceinline__ unsigned long long ffma2(unsigned long long a,
                                                    unsigned long long b,
                                                    unsigned long long c) {
    unsigned long long d;
    asm("fma.rn.f32x2 %0, %1, %2, %3;" : "=l"(d) : "l"(a), "l"(b), "l"(c));
    return d;
}
__device__ __forceinline__ unsigned long long pack2(float x) {
    unsigned long long r;
    asm("mov.b64 %0, {%1, %1};" : "=l"(r) : "f"(x));
    return r;
}
__device__ __forceinline__ float2 unpack2(unsigned long long v) {
    float2 r;
    asm("mov.b64 {%0, %1}, %2;" : "=f"(r.x), "=f"(r.y) : "l"(v));
    return r;
}

// ---------- Kernel A: Wh = h @ W  (8192x128 @ 128x128) ----------
// 128 CTAs x 64 rows. W (64KB) + h-tile (32KB) in dynamic smem.
__global__ void __launch_bounds__(THREADS) wh_kernel(const float* __restrict__ h,
                                                     const float* __restrict__ W) {
    extern __shared__ float sm[];
    float* sW = sm;                 // 128*128
    float* sh = sm + FDIM * FDIM;   // 64*128
    int tid = threadIdx.x;
    int row0 = blockIdx.x * 64;
    for (int i = tid; i < FDIM * FDIM; i += THREADS) sW[i] = W[i];
    for (int i = tid; i < 64 * FDIM; i += THREADS) sh[i] = h[row0 * FDIM + i];
    __syncthreads();
    int c = tid & 127;
    int r0 = (tid >> 7) * 32;
    for (int r = r0; r < r0 + 32; r++) {
        float acc = 0.f;
        #pragma unroll 8
        for (int k = 0; k < FDIM; k++)
            acc = fmaf(sh[r * FDIM + k], sW[k * FDIM + c], acc);
        g_Wh[(row0 + r) * FDIM + c] = acc;
    }
}

// ---------- Kernel B: f1 = Wh@a1, f2 = Wh@a2 ----------
// 1024 CTAs x 8 warps; one warp per row.
__global__ void fvec_kernel(const float* __restrict__ a) {
    int i = blockIdx.x * 8 + (threadIdx.x >> 5);
    int lane = threadIdx.x & 31;
    float4 v  = *(const float4*)(g_Wh + i * FDIM + lane * 4);
    float4 a1 = *(const float4*)(a + lane * 4);
    float4 a2 = *(const float4*)(a + FDIM + lane * 4);
    float s1 = v.x * a1.x + v.y * a1.y + v.z * a1.z + v.w * a1.w;
    float s2 = v.x * a2.x + v.y * a2.y + v.z * a2.z + v.w * a2.w;
    #pragma unroll
    for (int o = 16; o > 0; o >>= 1) {
        s1 += __shfl_xor_sync(0xffffffffu, s1, o);
        s2 += __shfl_xor_sync(0xffffffffu, s2, o);
    }
    if (lane == 0) { g_f1[i] = s1; g_f2[i] = s2; }
}

// ---------- Kernel C: main fused GAT ----------
// 128 CTAs, each owns 64 output rows. Per 128-j chunk:
//   phase 1: coalesced adj read -> w = mask * exp(leaky(f1[i]+f2[j])) into smem,
//            warp-shfl row partial sums into Spart (deterministic, no atomics)
//   phase 2: f32x2 register-tiled GEMM: acc[64x128] += w[64x128] @ Wh_tile[128x128]
// End: out = acc / rowsum.
__global__ void __launch_bounds__(THREADS) gat_main_kernel(const int* __restrict__ adj,
                                                           float* __restrict__ out) {
    extern __shared__ float sm[];
    float* whs   = sm;                 // BJ*FDIM = 16384 floats (Wh tile, [k][t])
    float* ws    = whs + BJ * FDIM;    // BI*BJ   = 8192 floats  (weights, [i][jj])
    float* sf1   = ws + BI * BJ;       // 64
    float* Spart = sf1 + BI;           // 64*4 partial row sums

    int tid = threadIdx.x;
    int i0 = blockIdx.x * BI;
    int tt = tid & 15;          // t-group: cols tt*4..+3 and 64+tt*4..+3
    int ti = tid >> 4;          // i-group: rows ti*4..+3
    int jj = tid & 127;
    int ibase = tid >> 7;       // 0 or 1
    int wq = (tid >> 5) & 3;    // warp-within-row-group

    if (tid < BI) sf1[tid] = g_f1[i0 + tid];
    if (tid < BI * 4) Spart[tid] = 0.f;

    unsigned long long acc[4][4];
    #pragma unroll
    for (int m = 0; m < 4; m++)
        #pragma unroll
        for (int p = 0; p < 4; p++) acc[m][p] = 0ull;

    __syncthreads();

    for (int jc = 0; jc < NNODES / BJ; jc++) {
        int j0 = jc * BJ;

        // ---- load Wh tile (64KB, coalesced float4 copy; L2-resident source) ----
        {
            const float4* src = (const float4*)(g_Wh + j0 * FDIM);
            float4* dst = (float4*)whs;
            #pragma unroll
            for (int x = 0; x < (BJ * FDIM / 4) / THREADS; x++)
                dst[tid + x * THREADS] = src[tid + x * THREADS];
        }

        // ---- compute weight tile + row partial sums ----
        float f2v = g_f2[j0 + jj];
        #pragma unroll 4
        for (int s = 0; s < 32; s++) {
            int il = s * 2 + ibase;
            int av = adj[(i0 + il) * NNODES + j0 + jj];   // coalesced 512B/row
            float e = sf1[il] + f2v;
            float el = fmaxf(e, 0.2f * e);                // leaky relu
            float w = fast_exp(el);
            w = (av > 0) ? w : 0.f;
            ws[il * BJ + jj] = w;                         // conflict-free STS
            float pr = w;
            #pragma unroll
            for (int o = 16; o > 0; o >>= 1)
                pr += __shfl_xor_sync(0xffffffffu, pr, o);
            if ((tid & 31) == 0) Spart[il * 4 + wq] += pr; // unique writer slot
        }
        __syncthreads();

        // ---- f32x2 GEMM microkernel: 4 rows x 8 cols per thread ----
        const float* wrow = ws + (ti * 4) * BJ;
        const float* wc = whs + tt * 4;
        #pragma unroll 8
        for (int k = 0; k < BJ; k++) {
            ulonglong2 bA = *(const ulonglong2*)(wc + k * FDIM);        // cols tt*4..+3
            ulonglong2 bB = *(const ulonglong2*)(wc + k * FDIM + 64);   // cols 64+tt*4..+3
            #pragma unroll
            for (int m = 0; m < 4; m++) {
                unsigned long long w2 = pack2(wrow[m * BJ + k]);        // broadcast LDS
                acc[m][0] = ffma2(w2, bA.x, acc[m][0]);
                acc[m][1] = ffma2(w2, bA.y, acc[m][1]);
                acc[m][2] = ffma2(w2, bB.x, acc[m][2]);
                acc[m][3] = ffma2(w2, bB.y, acc[m][3]);
            }
        }
        __syncthreads();
    }

    // ---- normalize + store ----
    #pragma unroll
    for (int m = 0; m < 4; m++) {
        int il = ti * 4 + m;
        float S = Spart[il * 4] + Spart[il * 4 + 1] + Spart[il * 4 + 2] + Spart[il * 4 + 3];
        float inv = 1.0f / S;
        float2 r0 = unpack2(acc[m][0]);
        float2 r1 = unpack2(acc[m][1]);
        float2 r2 = unpack2(acc[m][2]);
        float2 r3 = unpack2(acc[m][3]);
        float4 o1 = make_float4(r0.x * inv, r0.y * inv, r1.x * inv, r1.y * inv);
        float4 o2 = make_float4(r2.x * inv, r2.y * inv, r3.x * inv, r3.y * inv);
        *(float4*)(out + (size_t)(i0 + il) * FDIM + tt * 4) = o1;
        *(float4*)(out + (size_t)(i0 + il) * FDIM + 64 + tt * 4) = o2;
    }
}

// ---------- launch ----------
extern "C" void kernel_launch(void* const* d_in, const int* in_sizes, int n_in,
                              void* d_out, int out_size) {
    const float* h   = (const float*)d_in[0];
    const int*   adj = (const int*)d_in[1];
    const float* W   = (const float*)d_in[2];
    const float* a   = (const float*)d_in[3];
    float* out = (float*)d_out;

    (void)in_sizes; (void)n_in; (void)out_size;

    cudaFuncSetAttribute(wh_kernel, cudaFuncAttributeMaxDynamicSharedMemorySize, 98304);
    cudaFuncSetAttribute(gat_main_kernel, cudaFuncAttributeMaxDynamicSharedMemorySize, 100352);

    wh_kernel<<<NNODES / 64, THREADS, 98304>>>(h, W);
    fvec_kernel<<<NNODES / 8, 256>>>(a);
    size_t smem_main = (size_t)(BJ * FDIM + BI * BJ + BI + BI * 4) * sizeof(float);
    gat_main_kernel<<<NNODES / BI, THREADS, smem_main>>>(adj, out);
}

// round 5
// speedup vs baseline: 3.8295x; 3.8295x over previous
#include <cuda_runtime.h>
#include <cuda_fp16.h>
#include <cstdint>

#define NN 8192
#define FD 128

// ---------------- global scratch (allocation-free rule) ----------------
__device__ __half g_Bhi[NN * FD];     // Wh fp16 hi
__device__ __half g_Blo[NN * FD];     // Wh fp16 lo residual
__device__ float  g_F1[NN];           // Wh @ a1
__device__ float  g_F2[NN];           // Wh @ a2
__device__ float4 g_E1[NN];           // {f1, e^f1, e^{0.2 f1}, 0}
__device__ float4 g_E2[NN];           // {f2, e^f2, e^{0.2 f2}, 0}
__device__ float  g_Pnum[2 * NN * FD];// partial numerators (2 j-halves)
__device__ float  g_Pden[2 * NN];     // partial denominators

// ---------------- helpers ----------------
__device__ __forceinline__ uint32_t smem_u32(const void* p) {
    uint32_t a;
    asm("{ .reg .u64 t; cvta.to.shared.u64 t, %1; cvt.u32.u64 %0, t; }" : "=r"(a) : "l"(p));
    return a;
}
__device__ __forceinline__ float slctf(float a, float b, float c) {
    float d; asm("slct.f32.f32 %0, %1, %2, %3;" : "=f"(d) : "f"(a), "f"(b), "f"(c));
    return d;  // c >= 0 ? a : b
}
__device__ __forceinline__ uint32_t f16x2(float hi, float lo) {
    uint32_t r; asm("cvt.rn.f16x2.f32 %0, %1, %2;" : "=r"(r) : "f"(hi), "f"(lo));
    return r;  // memory order: [lo, hi]
}
__device__ __forceinline__ float h2f_lo(uint32_t v) {
    return __half2float(__ushort_as_half((unsigned short)(v & 0xFFFFu)));
}
__device__ __forceinline__ float h2f_hi(uint32_t v) {
    return __half2float(__ushort_as_half((unsigned short)(v >> 16)));
}
__device__ __forceinline__ void cp16(uint32_t dst, const void* src) {
    asm volatile("cp.async.cg.shared.global [%0], [%1], 16;" :: "r"(dst), "l"(src));
}
__device__ __forceinline__ void cp_commit() {
    asm volatile("cp.async.commit_group;" ::: "memory");
}
__device__ __forceinline__ void cp_wait1() {
    asm volatile("cp.async.wait_group 1;" ::: "memory");
}
__device__ __forceinline__ void ldsm_x4(uint32_t* r, uint32_t addr) {
    asm volatile("ldmatrix.sync.aligned.m8n8.x4.shared.b16 {%0,%1,%2,%3}, [%4];"
                 : "=r"(r[0]), "=r"(r[1]), "=r"(r[2]), "=r"(r[3]) : "r"(addr));
}
__device__ __forceinline__ void ldsm_x2t(uint32_t* r, uint32_t addr) {
    asm volatile("ldmatrix.sync.aligned.m8n8.x2.trans.shared.b16 {%0,%1}, [%2];"
                 : "=r"(r[0]), "=r"(r[1]) : "r"(addr));
}
__device__ __forceinline__ void mma16816(float* d, const uint32_t* a, const uint32_t* b) {
    asm volatile(
        "mma.sync.aligned.m16n8k16.row.col.f32.f16.f16.f32 "
        "{%0,%1,%2,%3},{%4,%5,%6,%7},{%8,%9},{%0,%1,%2,%3};"
        : "+f"(d[0]), "+f"(d[1]), "+f"(d[2]), "+f"(d[3])
        : "r"(a[0]), "r"(a[1]), "r"(a[2]), "r"(a[3]), "r"(b[0]), "r"(b[1]));
}

// ---------------- Kernel A: Wh = h @ W, fused f1/f2 + fp16 hi/lo split ----------------
// 256 CTAs x 32 rows, 256 threads; thread = (row, 16-col segment).
__global__ void __launch_bounds__(256) wh_kernel(const float* __restrict__ h,
                                                 const float* __restrict__ W,
                                                 const float* __restrict__ a) {
    extern __shared__ float sm[];
    float* sW = sm;              // 128x128
    float* sh = sm + 16384;      // 32x128
    float* sa = sh + 4096;       // 256
    int tid = threadIdx.x;
    int i0 = blockIdx.x * 32;

    {
        float4* wd = (float4*)sW; const float4* ws = (const float4*)W;
        #pragma unroll
        for (int p = 0; p < 16; p++) wd[tid + p * 256] = ws[tid + p * 256];
        float4* hd = (float4*)sh; const float4* hs = (const float4*)(h + (size_t)i0 * FD);
        #pragma unroll
        for (int p = 0; p < 4; p++) hd[tid + p * 256] = hs[tid + p * 256];
        sa[tid] = a[tid];
    }
    __syncthreads();

    int row = tid >> 3;
    int seg = (tid & 7) * 16;
    float acc[16];
    #pragma unroll
    for (int q = 0; q < 16; q++) acc[q] = 0.f;

    #pragma unroll 4
    for (int k = 0; k < FD; k++) {
        float hv = sh[row * FD + k];
        const float* wr = sW + k * FD + seg;
        #pragma unroll
        for (int q = 0; q < 16; q++) acc[q] = fmaf(hv, wr[q], acc[q]);
    }

    // fp16 hi/lo split, packed
    uint32_t hp[8], lp[8];
    #pragma unroll
    for (int q = 0; q < 8; q++) {
        float a0 = acc[2 * q], a1 = acc[2 * q + 1];
        uint32_t hh = f16x2(a1, a0);
        float r0 = a0 - h2f_lo(hh);
        float r1 = a1 - h2f_hi(hh);
        hp[q] = hh;
        lp[q] = f16x2(r1, r0);
    }
    {
        uint32_t* dh = (uint32_t*)(g_Bhi + (size_t)(i0 + row) * FD + seg);
        uint32_t* dl = (uint32_t*)(g_Blo + (size_t)(i0 + row) * FD + seg);
        *(uint4*)dh = make_uint4(hp[0], hp[1], hp[2], hp[3]);
        *(uint4*)(dh + 4) = make_uint4(hp[4], hp[5], hp[6], hp[7]);
        *(uint4*)dl = make_uint4(lp[0], lp[1], lp[2], lp[3]);
        *(uint4*)(dl + 4) = make_uint4(lp[4], lp[5], lp[6], lp[7]);
    }

    // f1/f2 partials (8 lanes per row, shfl reduce)
    float p1 = 0.f, p2 = 0.f;
    #pragma unroll
    for (int q = 0; q < 16; q++) {
        p1 = fmaf(acc[q], sa[seg + q], p1);
        p2 = fmaf(acc[q], sa[128 + seg + q], p2);
    }
    #pragma unroll
    for (int o = 1; o < 8; o <<= 1) {
        p1 += __shfl_xor_sync(0xffffffffu, p1, o);
        p2 += __shfl_xor_sync(0xffffffffu, p2, o);
    }
    if ((tid & 7) == 0) { g_F1[i0 + row] = p1; g_F2[i0 + row] = p2; }
}

// ---------------- Kernel B: exp vectors ----------------
__global__ void evec_kernel() {
    int i = blockIdx.x * 256 + threadIdx.x;
    float f1 = g_F1[i], f2 = g_F2[i];
    g_E1[i] = make_float4(f1, expf(f1), expf(0.2f * f1), 0.f);
    g_E2[i] = make_float4(f2, expf(f2), expf(0.2f * f2), 0.f);
}

// ---------------- Kernel C: main fused GAT (HMMA mma.sync) ----------------
// 128 CTAs = 64 row-groups x 2 j-halves; 256 threads (8 warps, 4x2).
// A tile: 128 rows x 64 k (fp16 weights), padded stride 72 halves (144B).
// B tiles: 64 k x 128 cols (hi + lo), padded stride 136 halves (272B).
#define ABUF 18432
#define BBUF 17408
#define OFF_A 0
#define OFF_BH (2 * ABUF)            // 36864
#define OFF_BL (OFF_BH + 2 * BBUF)   // 71680
#define OFF_E1 (OFF_BL + 2 * BBUF)   // 106496
#define SMEM_MAIN (OFF_E1 + 128 * 16)// 108544

__device__ __forceinline__ void gen_chunk(char* smem, int buf, int i0, int jcol0,
                                          const int* __restrict__ adj, int lane, int wid) {
    const float4* sE1 = (const float4*)(smem + OFF_E1);
    int jj = (lane & 15) * 4;
    int rowpar = lane >> 4;
    float4 e2[4];
    #pragma unroll
    for (int q = 0; q < 4; q++) e2[q] = g_E2[jcol0 + jj + q];
    int4 av[8];
    #pragma unroll
    for (int p = 0; p < 8; p++) {
        int row = p * 16 + wid * 2 + rowpar;
        av[p] = *(const int4*)(adj + (size_t)(i0 + row) * NN + jcol0 + jj);
    }
    char* A = smem + OFF_A + buf * ABUF;
    #pragma unroll
    for (int p = 0; p < 8; p++) {
        int row = p * 16 + wid * 2 + rowpar;
        float4 e1 = sE1[row];
        float w[4];
        int m0 = av[p].x, m1 = av[p].y, m2 = av[p].z, m3 = av[p].w;
        #pragma unroll
        for (int q = 0; q < 4; q++) {
            float f2x = (q == 0) ? e2[0].x : (q == 1) ? e2[1].x : (q == 2) ? e2[2].x : e2[3].x;
            float Ep  = (q == 0) ? e2[0].y : (q == 1) ? e2[1].y : (q == 2) ? e2[2].y : e2[3].y;
            float En  = (q == 0) ? e2[0].z : (q == 1) ? e2[1].z : (q == 2) ? e2[2].z : e2[3].z;
            float z = e1.x + f2x;
            float aE = slctf(e1.y, e1.z, z);
            float bE = slctf(Ep, En, z);
            w[q] = aE * bE;
        }
        if (m0 <= 0) w[0] = 0.f;
        if (m1 <= 0) w[1] = 0.f;
        if (m2 <= 0) w[2] = 0.f;
        if (m3 <= 0) w[3] = 0.f;
        uint32_t h01 = f16x2(w[1], w[0]);
        uint32_t h23 = f16x2(w[3], w[2]);
        *(uint2*)(A + row * 144 + (lane & 15) * 8) = make_uint2(h01, h23);
    }
}

__device__ __forceinline__ void stage_B(int buf, int jcol0, int tid, uint32_t sb) {
    #pragma unroll
    for (int p = 0; p < 4; p++) {
        int idx = tid + p * 256;
        int row = idx >> 4, seg = idx & 15;
        uint32_t d0 = sb + OFF_BH + buf * BBUF + row * 272 + seg * 16;
        uint32_t d1 = sb + OFF_BL + buf * BBUF + row * 272 + seg * 16;
        cp16(d0, g_Bhi + (size_t)(jcol0 + row) * FD + seg * 8);
        cp16(d1, g_Blo + (size_t)(jcol0 + row) * FD + seg * 8);
    }
}

__global__ void __launch_bounds__(256, 1) gat_main_kernel(const int* __restrict__ adj) {
    extern __shared__ char smem[];
    uint32_t sb = smem_u32(smem);
    int tid = threadIdx.x, lane = tid & 31, wid = tid >> 5;
    int grp = blockIdx.x >> 1, half = blockIdx.x & 1;
    int i0 = grp * 128, jbase = half * 4096;
    int wr = wid & 3, wc = wid >> 2;

    if (tid < 128) ((float4*)(smem + OFF_E1))[tid] = g_E1[i0 + tid];
    __syncthreads();

    float acc[2][8][4];
    float dacc[2][4];
    #pragma unroll
    for (int s = 0; s < 2; s++) {
        #pragma unroll
        for (int tn = 0; tn < 8; tn++)
            #pragma unroll
            for (int q = 0; q < 4; q++) acc[s][tn][q] = 0.f;
        #pragma unroll
        for (int q = 0; q < 4; q++) dacc[s][q] = 0.f;
    }
    uint32_t bones[2];
    bones[0] = bones[1] = (lane < 4) ? 0x3C003C00u : 0u;  // ones column fragment

    stage_B(0, jbase, tid, sb);
    cp_commit();
    gen_chunk(smem, 0, i0, jbase, adj, lane, wid);

    for (int c = 0; c < 64; c++) {
        if (c + 1 < 64) {
            stage_B((c + 1) & 1, jbase + (c + 1) * 64, tid, sb);
            cp_commit();
            gen_chunk(smem, (c + 1) & 1, i0, jbase + (c + 1) * 64, adj, lane, wid);
        } else {
            cp_commit();  // empty group keeps wait_group accounting uniform
        }
        cp_wait1();
        __syncthreads();

        int buf = c & 1;
        uint32_t Ab = sb + OFF_A + buf * ABUF;
        uint32_t Bh = sb + OFF_BH + buf * BBUF;
        uint32_t Bl = sb + OFF_BL + buf * BBUF;
        #pragma unroll
        for (int ks = 0; ks < 4; ks++) {
            uint32_t afr[2][4];
            #pragma unroll
            for (int s = 0; s < 2; s++)
                ldsm_x4(afr[s], Ab + (wr * 32 + s * 16 + (lane & 15)) * 144
                                   + ks * 32 + (lane >> 4) * 16);
            #pragma unroll
            for (int tn = 0; tn < 8; tn++) {
                uint32_t boff = (ks * 16 + (lane & 15)) * 272 + (wc * 8 + tn) * 16;
                uint32_t bh[2], bl[2];
                ldsm_x2t(bh, Bh + boff);
                ldsm_x2t(bl, Bl + boff);
                mma16816(acc[0][tn], afr[0], bh);
                mma16816(acc[0][tn], afr[0], bl);
                mma16816(acc[1][tn], afr[1], bh);
                mma16816(acc[1][tn], afr[1], bl);
            }
            if (wc == 0) {
                mma16816(dacc[0], afr[0], bones);
                mma16816(dacc[1], afr[1], bones);
            }
        }
        __syncthreads();
    }

    // epilogue: write partial numerators + denominators
    int r0 = i0 + wr * 32;
    float* P = g_Pnum + (size_t)half * NN * FD;
    #pragma unroll
    for (int s = 0; s < 2; s++) {
        int rA = r0 + s * 16 + (lane >> 2);
        #pragma unroll
        for (int tn = 0; tn < 8; tn++) {
            int col = (wc * 8 + tn) * 8 + (lane & 3) * 2;
            *(float2*)&P[(size_t)rA * FD + col] = make_float2(acc[s][tn][0], acc[s][tn][1]);
            *(float2*)&P[(size_t)(rA + 8) * FD + col] = make_float2(acc[s][tn][2], acc[s][tn][3]);
        }
        if (wc == 0 && (lane & 3) == 0) {
            g_Pden[half * NN + rA] = dacc[s][0];
            g_Pden[half * NN + rA + 8] = dacc[s][2];
        }
    }
}

// ---------------- Kernel D: combine halves + softmax divide ----------------
__global__ void reduce_kernel(float* __restrict__ out) {
    int idx = blockIdx.x * 256 + threadIdx.x;  // 0 .. NN*FD-1
    int i = idx >> 7;
    float num = g_Pnum[idx] + g_Pnum[NN * FD + idx];
    float den = g_Pden[i] + g_Pden[NN + i];
    out[idx] = num / den;
}

// ---------------- launch ----------------
extern "C" void kernel_launch(void* const* d_in, const int* in_sizes, int n_in,
                              void* d_out, int out_size) {
    const float* h   = (const float*)d_in[0];
    const int*   adj = (const int*)d_in[1];
    const float* W   = (const float*)d_in[2];
    const float* a   = (const float*)d_in[3];
    float* out = (float*)d_out;
    (void)in_sizes; (void)n_in; (void)out_size;

    cudaFuncSetAttribute(wh_kernel, cudaFuncAttributeMaxDynamicSharedMemorySize, 82944);
    cudaFuncSetAttribute(gat_main_kernel, cudaFuncAttributeMaxDynamicSharedMemorySize, SMEM_MAIN);

    wh_kernel<<<NN / 32, 256, 82944>>>(h, W, a);
    evec_kernel<<<NN / 256, 256>>>();
    gat_main_kernel<<<128, 256, SMEM_MAIN>>>(adj);
    reduce_kernel<<<NN * FD / 256, 256>>>(out);
}

// round 6
// speedup vs baseline: 5.0295x; 1.3134x over previous
#include <cuda_runtime.h>
#include <cuda_fp16.h>
#include <cstdint>

#define NN 8192
#define FD 128

// ---------------- global scratch (allocation-free rule) ----------------
__device__ __half g_Bhi[NN * FD];     // Wh fp16
__device__ float  g_F1[NN];           // Wh @ a1
__device__ float  g_F2[NN];           // Wh @ a2
__device__ float4 g_E1[NN];           // {f1, e^f1, e^{0.2 f1}, 0}
__device__ float4 g_E2[NN];           // {f2, e^f2, e^{0.2 f2}, 0}
__device__ float  g_Pnum[2 * NN * FD];// partial numerators (2 j-halves)
__device__ float  g_Pden[2 * NN];     // partial denominators

// ---------------- helpers ----------------
__device__ __forceinline__ uint32_t smem_u32(const void* p) {
    uint32_t a;
    asm("{ .reg .u64 t; cvta.to.shared.u64 t, %1; cvt.u32.u64 %0, t; }" : "=r"(a) : "l"(p));
    return a;
}
__device__ __forceinline__ float slctf(float a, float b, float c) {
    float d; asm("slct.f32.f32 %0, %1, %2, %3;" : "=f"(d) : "f"(a), "f"(b), "f"(c));
    return d;  // c >= 0 ? a : b
}
__device__ __forceinline__ uint32_t f16x2(float hi, float lo) {
    uint32_t r; asm("cvt.rn.f16x2.f32 %0, %1, %2;" : "=r"(r) : "f"(hi), "f"(lo));
    return r;  // memory order: [lo, hi]
}
__device__ __forceinline__ void cp16(uint32_t dst, const void* src) {
    asm volatile("cp.async.cg.shared.global [%0], [%1], 16;" :: "r"(dst), "l"(src));
}
__device__ __forceinline__ void cp_commit() {
    asm volatile("cp.async.commit_group;" ::: "memory");
}
__device__ __forceinline__ void cp_wait1() {
    asm volatile("cp.async.wait_group 1;" ::: "memory");
}
__device__ __forceinline__ void ldsm_x4(uint32_t* r, uint32_t addr) {
    asm volatile("ldmatrix.sync.aligned.m8n8.x4.shared.b16 {%0,%1,%2,%3}, [%4];"
                 : "=r"(r[0]), "=r"(r[1]), "=r"(r[2]), "=r"(r[3]) : "r"(addr));
}
__device__ __forceinline__ void ldsm_x4t(uint32_t* r, uint32_t addr) {
    asm volatile("ldmatrix.sync.aligned.m8n8.x4.trans.shared.b16 {%0,%1,%2,%3}, [%4];"
                 : "=r"(r[0]), "=r"(r[1]), "=r"(r[2]), "=r"(r[3]) : "r"(addr));
}
__device__ __forceinline__ void mma16816(float* d, const uint32_t* a, const uint32_t* b) {
    asm volatile(
        "mma.sync.aligned.m16n8k16.row.col.f32.f16.f16.f32 "
        "{%0,%1,%2,%3},{%4,%5,%6,%7},{%8,%9},{%0,%1,%2,%3};"
        : "+f"(d[0]), "+f"(d[1]), "+f"(d[2]), "+f"(d[3])
        : "r"(a[0]), "r"(a[1]), "r"(a[2]), "r"(a[3]), "r"(b[0]), "r"(b[1]));
}

// ---------------- Kernel A: Wh = h @ W, fused f1/f2 + fp16 convert ----------------
__global__ void __launch_bounds__(256) wh_kernel(const float* __restrict__ h,
                                                 const float* __restrict__ W,
                                                 const float* __restrict__ a) {
    extern __shared__ float sm[];
    float* sW = sm;              // 128x128
    float* sh = sm + 16384;      // 32x128
    float* sa = sh + 4096;       // 256
    int tid = threadIdx.x;
    int i0 = blockIdx.x * 32;

    {
        float4* wd = (float4*)sW; const float4* ws = (const float4*)W;
        #pragma unroll
        for (int p = 0; p < 16; p++) wd[tid + p * 256] = ws[tid + p * 256];
        float4* hd = (float4*)sh; const float4* hs = (const float4*)(h + (size_t)i0 * FD);
        #pragma unroll
        for (int p = 0; p < 4; p++) hd[tid + p * 256] = hs[tid + p * 256];
        sa[tid] = a[tid];
    }
    __syncthreads();

    int row = tid >> 3;
    int seg = (tid & 7) * 16;
    float acc[16];
    #pragma unroll
    for (int q = 0; q < 16; q++) acc[q] = 0.f;

    #pragma unroll 4
    for (int k = 0; k < FD; k++) {
        float hv = sh[row * FD + k];
        const float* wr = sW + k * FD + seg;
        #pragma unroll
        for (int q = 0; q < 16; q++) acc[q] = fmaf(hv, wr[q], acc[q]);
    }

    uint32_t hp[8];
    #pragma unroll
    for (int q = 0; q < 8; q++) hp[q] = f16x2(acc[2 * q + 1], acc[2 * q]);
    {
        uint32_t* dh = (uint32_t*)(g_Bhi + (size_t)(i0 + row) * FD + seg);
        *(uint4*)dh = make_uint4(hp[0], hp[1], hp[2], hp[3]);
        *(uint4*)(dh + 4) = make_uint4(hp[4], hp[5], hp[6], hp[7]);
    }

    float p1 = 0.f, p2 = 0.f;
    #pragma unroll
    for (int q = 0; q < 16; q++) {
        p1 = fmaf(acc[q], sa[seg + q], p1);
        p2 = fmaf(acc[q], sa[128 + seg + q], p2);
    }
    #pragma unroll
    for (int o = 1; o < 8; o <<= 1) {
        p1 += __shfl_xor_sync(0xffffffffu, p1, o);
        p2 += __shfl_xor_sync(0xffffffffu, p2, o);
    }
    if ((tid & 7) == 0) { g_F1[i0 + row] = p1; g_F2[i0 + row] = p2; }
}

// ---------------- Kernel B: exp vectors ----------------
__global__ void evec_kernel() {
    int i = blockIdx.x * 256 + threadIdx.x;
    float f1 = g_F1[i], f2 = g_F2[i];
    g_E1[i] = make_float4(f1, expf(f1), expf(0.2f * f1), 0.f);
    g_E2[i] = make_float4(f2, expf(f2), expf(0.2f * f2), 0.f);
}

// ---------------- Kernel C: main fused GAT (HMMA, prefetch-pipelined) ----------------
// 128 CTAs = 64 row-groups x 2 j-halves; 256 threads (8 warps, 4 row x 2 col).
// A: 128 x 64 fp16 weights, stride 144B. B: 64k x 128n fp16, stride 272B.
#define ABUF 18432
#define BBUF 17408
#define OFF_A 0
#define OFF_BH (2 * ABUF)              // 36864
#define OFF_E1 (OFF_BH + 2 * BBUF)     // 71680
#define SMEM_MAIN (OFF_E1 + 128 * 16)  // 73728

struct Pref {
    int4 av[8];
    float4 e2[4];
};

__device__ __forceinline__ void prefetch(Pref& P, int i0, int jcol0,
                                         const int* __restrict__ adj, int lane, int wid) {
    int jj = (lane & 15) * 4;
    int rowpar = lane >> 4;
    #pragma unroll
    for (int q = 0; q < 4; q++) P.e2[q] = g_E2[jcol0 + jj + q];
    #pragma unroll
    for (int p = 0; p < 8; p++) {
        int row = p * 16 + wid * 2 + rowpar;
        P.av[p] = *(const int4*)(adj + (size_t)(i0 + row) * NN + jcol0 + jj);
    }
}

__device__ __forceinline__ void gen_compute(char* smem, int buf, const Pref& P,
                                            int lane, int wid) {
    const float4* sE1 = (const float4*)(smem + OFF_E1);
    int rowpar = lane >> 4;
    char* A = smem + OFF_A + buf * ABUF;
    #pragma unroll
    for (int p = 0; p < 8; p++) {
        int row = p * 16 + wid * 2 + rowpar;
        float4 e1 = sE1[row];
        float w[4];
        #pragma unroll
        for (int q = 0; q < 4; q++) {
            float f2x = (q == 0) ? P.e2[0].x : (q == 1) ? P.e2[1].x : (q == 2) ? P.e2[2].x : P.e2[3].x;
            float Ep  = (q == 0) ? P.e2[0].y : (q == 1) ? P.e2[1].y : (q == 2) ? P.e2[2].y : P.e2[3].y;
            float En  = (q == 0) ? P.e2[0].z : (q == 1) ? P.e2[1].z : (q == 2) ? P.e2[2].z : P.e2[3].z;
            float z = e1.x + f2x;
            w[q] = slctf(e1.y, e1.z, z) * slctf(Ep, En, z);
        }
        if (P.av[p].x <= 0) w[0] = 0.f;
        if (P.av[p].y <= 0) w[1] = 0.f;
        if (P.av[p].z <= 0) w[2] = 0.f;
        if (P.av[p].w <= 0) w[3] = 0.f;
        *(uint2*)(A + row * 144 + (lane & 15) * 8) =
            make_uint2(f16x2(w[1], w[0]), f16x2(w[3], w[2]));
    }
}

__device__ __forceinline__ void stage_B(int buf, int jcol0, int tid, uint32_t sb) {
    #pragma unroll
    for (int p = 0; p < 4; p++) {
        int idx = tid + p * 256;
        int row = idx >> 4, seg = idx & 15;
        cp16(sb + OFF_BH + buf * BBUF + row * 272 + seg * 16,
             g_Bhi + (size_t)(jcol0 + row) * FD + seg * 8);
    }
}

__global__ void __launch_bounds__(256, 1) gat_main_kernel(const int* __restrict__ adj) {
    extern __shared__ char smem[];
    uint32_t sb = smem_u32(smem);
    int tid = threadIdx.x, lane = tid & 31, wid = tid >> 5;
    int grp = blockIdx.x >> 1, half = blockIdx.x & 1;
    int i0 = grp * 128, jbase = half * 4096;
    int wr = wid & 3, wc = wid >> 2;

    if (tid < 128) ((float4*)(smem + OFF_E1))[tid] = g_E1[i0 + tid];
    __syncthreads();

    float acc[2][8][4];
    float dacc[2][4];
    #pragma unroll
    for (int s = 0; s < 2; s++) {
        #pragma unroll
        for (int tn = 0; tn < 8; tn++)
            #pragma unroll
            for (int q = 0; q < 4; q++) acc[s][tn][q] = 0.f;
        #pragma unroll
        for (int q = 0; q < 4; q++) dacc[s][q] = 0.f;
    }
    uint32_t bones[2];
    bones[0] = bones[1] = (lane < 4) ? 0x3C003C00u : 0u;  // ones column fragment

    Pref P;
    prefetch(P, i0, jbase, adj, lane, wid);
    stage_B(0, jbase, tid, sb);
    cp_commit();
    gen_compute(smem, 0, P, lane, wid);

    for (int c = 0; c < 64; c++) {
        if (c + 1 < 64) {
            prefetch(P, i0, jbase + (c + 1) * 64, adj, lane, wid);  // LDG issue only
            stage_B((c + 1) & 1, jbase + (c + 1) * 64, tid, sb);
            cp_commit();
        } else {
            cp_commit();
        }
        cp_wait1();
        __syncthreads();   // A(c), B(c) visible to all

        int buf = c & 1;
        uint32_t Ab = sb + OFF_A + buf * ABUF;
        uint32_t Bh = sb + OFF_BH + buf * BBUF;
        #pragma unroll
        for (int ks = 0; ks < 4; ks++) {
            uint32_t afr[2][4];
            ldsm_x4(afr[0], Ab + (wr * 32 + (lane & 15)) * 144 + ks * 32 + (lane >> 4) * 16);
            ldsm_x4(afr[1], Ab + (wr * 32 + 16 + (lane & 15)) * 144 + ks * 32 + (lane >> 4) * 16);
            #pragma unroll
            for (int t2 = 0; t2 < 4; t2++) {
                uint32_t bf[4];   // {b0,b1} of tile 2*t2, {b0,b1} of tile 2*t2+1
                ldsm_x4t(bf, Bh + (ks * 16 + (lane & 7) + ((lane >> 3) & 1) * 8) * 272
                               + (wc * 8 + t2 * 2 + (lane >> 4)) * 16);
                mma16816(acc[0][2 * t2],     afr[0], bf);
                mma16816(acc[0][2 * t2 + 1], afr[0], bf + 2);
                mma16816(acc[1][2 * t2],     afr[1], bf);
                mma16816(acc[1][2 * t2 + 1], afr[1], bf + 2);
            }
            if (wc == 0) {
                mma16816(dacc[0], afr[0], bones);
                mma16816(dacc[1], afr[1], bones);
            }
        }

        if (c + 1 < 64) gen_compute(smem, (c + 1) & 1, P, lane, wid);
        __syncthreads();   // buffer-reuse guard before next stage_B / vs laggard MMA readers
    }

    // epilogue: write partial numerators + denominators
    int r0 = i0 + wr * 32;
    float* Pn = g_Pnum + (size_t)half * NN * FD;
    #pragma unroll
    for (int s = 0; s < 2; s++) {
        int rA = r0 + s * 16 + (lane >> 2);
        #pragma unroll
        for (int tn = 0; tn < 8; tn++) {
            int col = (wc * 8 + tn) * 8 + (lane & 3) * 2;
            *(float2*)&Pn[(size_t)rA * FD + col] = make_float2(acc[s][tn][0], acc[s][tn][1]);
            *(float2*)&Pn[(size_t)(rA + 8) * FD + col] = make_float2(acc[s][tn][2], acc[s][tn][3]);
        }
        if (wc == 0 && (lane & 3) == 0) {
            g_Pden[half * NN + rA] = dacc[s][0];
            g_Pden[half * NN + rA + 8] = dacc[s][2];
        }
    }
}

// ---------------- Kernel D: combine halves + softmax divide (vectorized) ----------------
__global__ void reduce_kernel(float* __restrict__ out) {
    int v = blockIdx.x * 256 + threadIdx.x;   // 0 .. NN*FD/4-1
    int i = v >> 5;                            // row (32 float4 per row)
    const float4* P0 = (const float4*)g_Pnum;
    const float4* P1 = (const float4*)(g_Pnum + NN * FD);
    float4 n0 = P0[v], n1 = P1[v];
    float inv = 1.0f / (g_Pden[i] + g_Pden[NN + i]);
    ((float4*)out)[v] = make_float4((n0.x + n1.x) * inv, (n0.y + n1.y) * inv,
                                    (n0.z + n1.z) * inv, (n0.w + n1.w) * inv);
}

// ---------------- launch ----------------
extern "C" void kernel_launch(void* const* d_in, const int* in_sizes, int n_in,
                              void* d_out, int out_size) {
    const float* h   = (const float*)d_in[0];
    const int*   adj = (const int*)d_in[1];
    const float* W   = (const float*)d_in[2];
    const float* a   = (const float*)d_in[3];
    float* out = (float*)d_out;
    (void)in_sizes; (void)n_in; (void)out_size;

    cudaFuncSetAttribute(wh_kernel, cudaFuncAttributeMaxDynamicSharedMemorySize, 82944);
    cudaFuncSetAttribute(gat_main_kernel, cudaFuncAttributeMaxDynamicSharedMemorySize, SMEM_MAIN);

    wh_kernel<<<NN / 32, 256, 82944>>>(h, W, a);
    evec_kernel<<<NN / 256, 256>>>();
    gat_main_kernel<<<128, 256, SMEM_MAIN>>>(adj);
    reduce_kernel<<<NN * FD / 4 / 256, 256>>>(out);
}